// round 16
// baseline (speedup 1.0000x reference)
#include <cuda_runtime.h>
#include <cuda_bf16.h>

// FokkerPlanck2D step, two-kernel scheme:
//  K1 (tiny, 3-way split): fold A + D + dt into 9 per-point stencil weight
//      planes, stored as bf16 (batch-independent, boundary logic baked in).
//      Center weight stored as (Wc - 1) so all stored weights are O(dt*coeff)
//      and bf16 quantization stays ~1e-4 relative (measured 2.7e-5).
//  K2 (hot, R9/R13/R15 structure): out = max(0, f_c + sum_9 w_o * f_nbr).
//      i-pencil blocks, 128 threads x float4 = full row, NBATCH=4 batches
//      share weights; f rows rotate through 6-wide register windows.
//      R16: two-stage zero-register f prefetch ladder:
//        prefetch.L2 [row i+3]  (DRAM -> L2, 2 iters ahead)
//        prefetch.L1 [row i+2]  (L2 -> L1, 1 iter ahead)
//      so the in-loop f LDG is an L1 hit. Weights NOT prefetched (R14 showed
//      weight prefetch just adds L2 pressure).
//      Known-bad (do not retry): shuffles (R5/R8), unroll (R7), bound-5 /
//      staged regs (R10), reg-prefetch (R11), reorder+__ldcs (R12),
//      weight prefetch (R14).
// Weight planes: 0:Wc-1 1:Wxp 2:Wxm 3:Wyp 4:Wym 5:Wpp 6:Wpm 7:Wmp 8:Wmm

static constexpr int NXC    = 512;
static constexpr int NYC    = 512;
static constexpr int ICH    = 16;
static constexpr int NBATCH = 4;
static constexpr int TPB    = NYC / 4;      // 128
static constexpr long PLANE = (long)NXC * NYC;

__device__ __nv_bfloat16 g_wh[9 * NXC * NYC];   // 4.7 MB scratch (L2-resident)

// p points at row[j0]; v[m] = p[m-1], halos zero-filled via L/R predicates.
__device__ __forceinline__ void win6_p(const float* __restrict__ p,
                                       bool Lg, bool Rg, float v[6]) {
    const float4 m4 = __ldg(reinterpret_cast<const float4*>(p));
    v[0] = Lg ? __ldg(p - 1) : 0.0f;
    v[1] = m4.x; v[2] = m4.y; v[3] = m4.z; v[4] = m4.w;
    v[5] = Rg ? __ldg(p + 4) : 0.0f;
}

__device__ __forceinline__ void store_w4_bf16(__nv_bfloat16* dst, const float w[4]) {
    __nv_bfloat162 lo = __floats2bfloat162_rn(w[0], w[1]);
    __nv_bfloat162 hi = __floats2bfloat162_rn(w[2], w[3]);
    uint2 st;
    st.x = *reinterpret_cast<const unsigned*>(&lo);
    st.y = *reinterpret_cast<const unsigned*>(&hi);
    *reinterpret_cast<uint2*>(dst) = st;
}

__global__ __launch_bounds__(TPB)
void fp2d_weights_kernel(const float* __restrict__ A,
                         const float* __restrict__ D,
                         const float* __restrict__ dtp) {
    const int tid = threadIdx.x;
    const int j0  = tid * 4;
    const bool L  = (tid > 0);
    const bool R  = (tid < TPB - 1);
    const int i   = blockIdx.x;
    const int grp = blockIdx.y;

    const float dt  = __ldg(dtp);
    const float hdt = 0.5f  * dt;
    const float qdt = 0.25f * dt;

    const float* A0 = A;
    const float* A1 = A + PLANE;
    const float* D0 = D;
    const float* D1 = D + PLANE;
    const float* D2 = D + 2 * PLANE;

    float w0[4], w1[4], w2[4];
    int p0, p1, p2;

    if (grp == 0) {
        // center-row weights: Wc-1 (0), Wyp(3), Wym(4)
        p0 = 0; p1 = 3; p2 = 4;
        const float4 d0 = __ldg(reinterpret_cast<const float4*>(D0 + (long)i * NYC + j0));
        float d1w[6], a1w[6];
        win6_p(D1 + (long)i * NYC + j0, L, R, d1w);
        win6_p(A1 + (long)i * NYC + j0, L, R, a1w);
        const float d0v[4] = {d0.x, d0.y, d0.z, d0.w};
        #pragma unroll
        for (int k = 0; k < 4; ++k) {
            w0[k] = -dt * (d0v[k] + d1w[k + 1]);     // Wc - 1 (small!)
            w1[k] = hdt * (d1w[k + 2] - a1w[k + 2]);
            w2[k] = hdt * (d1w[k]     + a1w[k]);
        }
    } else if (grp == 1) {
        // i+1-row weights: Wxp(1), Wpp(5), Wpm(6)
        p0 = 1; p1 = 5; p2 = 6;
        const int ip = i + 1;
        if (ip < NXC) {
            const float4 a0 = __ldg(reinterpret_cast<const float4*>(A0 + (long)ip * NYC + j0));
            const float4 d0 = __ldg(reinterpret_cast<const float4*>(D0 + (long)ip * NYC + j0));
            const float a0v[4] = {a0.x, a0.y, a0.z, a0.w};
            const float d0v[4] = {d0.x, d0.y, d0.z, d0.w};
            float d2w[6];
            win6_p(D2 + (long)ip * NYC + j0, L, R, d2w);
            #pragma unroll
            for (int k = 0; k < 4; ++k) {
                w0[k] =  hdt * (d0v[k] - a0v[k]);
                w1[k] =  qdt * d2w[k + 2];
                w2[k] = -qdt * d2w[k];
            }
        } else {
            #pragma unroll
            for (int k = 0; k < 4; ++k) { w0[k] = 0.f; w1[k] = 0.f; w2[k] = 0.f; }
        }
    } else {
        // i-1-row weights: Wxm(2), Wmp(7), Wmm(8)
        p0 = 2; p1 = 7; p2 = 8;
        const int im = i - 1;
        if (im >= 0) {
            const float4 a0 = __ldg(reinterpret_cast<const float4*>(A0 + (long)im * NYC + j0));
            const float4 d0 = __ldg(reinterpret_cast<const float4*>(D0 + (long)im * NYC + j0));
            const float a0v[4] = {a0.x, a0.y, a0.z, a0.w};
            const float d0v[4] = {d0.x, d0.y, d0.z, d0.w};
            float d2w[6];
            win6_p(D2 + (long)im * NYC + j0, L, R, d2w);
            #pragma unroll
            for (int k = 0; k < 4; ++k) {
                w0[k] =  hdt * (d0v[k] + a0v[k]);
                w1[k] = -qdt * d2w[k + 2];
                w2[k] =  qdt * d2w[k];
            }
        } else {
            #pragma unroll
            for (int k = 0; k < 4; ++k) { w0[k] = 0.f; w1[k] = 0.f; w2[k] = 0.f; }
        }
    }

    const long off = (long)i * NYC + j0;
    store_w4_bf16(g_wh + p0 * PLANE + off, w0);
    store_w4_bf16(g_wh + p1 * PLANE + off, w1);
    store_w4_bf16(g_wh + p2 * PLANE + off, w2);
}

__global__ __launch_bounds__(TPB, 4)
void fp2d_step_kernel(const float* __restrict__ f,
                      float* __restrict__ out) {
    const int tid = threadIdx.x;
    const int j0  = tid * 4;
    const bool L  = (tid > 0);
    const bool R  = (tid < TPB - 1);
    const bool pfl = ((tid & 7) == 0);   // one lane per 128B line
    const int i0  = blockIdx.x * ICH;
    const long b0 = (long)blockIdx.y * NBATCH;

    // single base pointers; batch/plane offsets become LDG/STG immediates
    const float* fbase = f   + b0 * PLANE + (long)i0 * NYC + j0;  // row i0
    float*       obase = out + b0 * PLANE + (long)i0 * NYC + j0;
    const __nv_bfloat16* wbase = g_wh + (long)i0 * NYC + j0;

    // f windows: [m] = f[row][j0+m-1], rotated along i
    float fm[NBATCH][6], fc[NBATCH][6], fp[NBATCH][6];

    // ---------------- prologue: f rows i0-1 and i0 ----------------
    if (i0 > 0) {
        #pragma unroll
        for (int b = 0; b < NBATCH; ++b)
            win6_p(fbase + b * PLANE - NYC, L, R, fm[b]);
    } else {
        #pragma unroll
        for (int b = 0; b < NBATCH; ++b)
            #pragma unroll
            for (int m = 0; m < 6; ++m) fm[b][m] = 0.0f;
    }
    #pragma unroll
    for (int b = 0; b < NBATCH; ++b)
        win6_p(fbase + b * PLANE, L, R, fc[b]);
    // warm the ladder: row i0+1 -> L1, row i0+2 -> L2 (both always valid)
    if (pfl) {
        #pragma unroll
        for (int b = 0; b < NBATCH; ++b) {
            const float* p1 = fbase + b * PLANE + NYC;
            const float* p2 = fbase + b * PLANE + 2 * NYC;
            asm volatile("prefetch.global.L1 [%0];" :: "l"(p1));
            asm volatile("prefetch.global.L2 [%0];" :: "l"(p2));
        }
    }

    // ---------------- main i-march ----------------
    for (int it = 0; it < ICH; ++it) {
        const bool up_ok = (i0 + it + 1) < NXC;

        // 1) load f row i+1 (L1-hot via the prefetch ladder)
        if (up_ok) {
            #pragma unroll
            for (int b = 0; b < NBATCH; ++b)
                win6_p(fbase + b * PLANE + NYC, L, R, fp[b]);
        } else {
            #pragma unroll
            for (int b = 0; b < NBATCH; ++b)
                #pragma unroll
                for (int m = 0; m < 6; ++m) fp[b][m] = 0.0f;
        }

        // 1b) zero-register prefetch ladder (no allocation impact):
        //     row i+3 DRAM->L2, row i+2 L2->L1.
        if (pfl) {
            if ((i0 + it + 3) < NXC) {
                #pragma unroll
                for (int b = 0; b < NBATCH; ++b) {
                    const float* pp = fbase + b * PLANE + 3 * NYC;
                    asm volatile("prefetch.global.L2 [%0];" :: "l"(pp));
                }
            }
            if ((i0 + it + 2) < NXC) {
                #pragma unroll
                for (int b = 0; b < NBATCH; ++b) {
                    const float* pp = fbase + b * PLANE + 2 * NYC;
                    asm volatile("prefetch.global.L1 [%0];" :: "l"(pp));
                }
            }
        }

        // 2) load the 9 bf16 weight vectors for row i (L2-hot, 8B each)
        uint2 wr[9];
        #pragma unroll
        for (int p = 0; p < 9; ++p)
            wr[p] = __ldg(reinterpret_cast<const uint2*>(wbase + p * PLANE));
        float wf[9][4];
        #pragma unroll
        for (int p = 0; p < 9; ++p) {
            const __nv_bfloat162 lo = *reinterpret_cast<const __nv_bfloat162*>(&wr[p].x);
            const __nv_bfloat162 hi = *reinterpret_cast<const __nv_bfloat162*>(&wr[p].y);
            const float2 flo = __bfloat1622float2(lo);
            const float2 fhi = __bfloat1622float2(hi);
            wf[p][0] = flo.x; wf[p][1] = flo.y;
            wf[p][2] = fhi.x; wf[p][3] = fhi.y;
        }

        // 3) compute + streaming-store outputs for row i
        //    v = f_c + (Wc-1)*f_c + axis/diag terms   (Wc split for bf16)
        #pragma unroll
        for (int b = 0; b < NBATCH; ++b) {
            float rv[4];
            #pragma unroll
            for (int k = 0; k < 4; ++k) {
                float v = fc[b][k + 1];
                v += wf[0][k] * fc[b][k + 1];
                v += wf[1][k] * fp[b][k + 1];
                v += wf[2][k] * fm[b][k + 1];
                v += wf[3][k] * fc[b][k + 2];
                v += wf[4][k] * fc[b][k];
                v += wf[5][k] * fp[b][k + 2];
                v += wf[6][k] * fp[b][k];
                v += wf[7][k] * fm[b][k + 2];
                v += wf[8][k] * fm[b][k];
                rv[k] = fmaxf(v, 0.0f);
            }
            float4 res;
            res.x = rv[0]; res.y = rv[1]; res.z = rv[2]; res.w = rv[3];
            __stcs(reinterpret_cast<float4*>(obase + b * PLANE), res);
        }

        // 4) rotate f windows (fp -> fc -> fm), advance bases
        #pragma unroll
        for (int b = 0; b < NBATCH; ++b)
            #pragma unroll
            for (int m = 0; m < 6; ++m) {
                fm[b][m] = fc[b][m];
                fc[b][m] = fp[b][m];
            }
        fbase += NYC;
        obase += NYC;
        wbase += NYC;
    }
}

extern "C" void kernel_launch(void* const* d_in, const int* in_sizes, int n_in,
                              void* d_out, int out_size) {
    const float* f  = (const float*)d_in[0];
    const float* A  = (const float*)d_in[1];
    const float* D  = (const float*)d_in[2];
    const float* dt = (const float*)d_in[3];
    float* out = (float*)d_out;

    const int plane = NXC * NYC;
    const int B = in_sizes[0] / plane;   // 128

    dim3 wgrid(NXC, 3);
    fp2d_weights_kernel<<<wgrid, TPB>>>(A, D, dt);
    dim3 grid(NXC / ICH, B / NBATCH);    // (32, 32)
    fp2d_step_kernel<<<grid, TPB>>>(f, out);
}

// round 17
// speedup vs baseline: 1.1507x; 1.1507x over previous
#include <cuda_runtime.h>
#include <cuda_bf16.h>

// FokkerPlanck2D step, two-kernel scheme with PDL overlap:
//  K1 (tiny, 3-way split): fold A + D + dt into 9 per-point bf16 stencil
//      weight planes (center stored as Wc-1 so bf16 error ~1e-4; measured
//      rel_err 2.7e-5). Ends with griddepcontrol.launch_dependents.
//  K2 (hot, R15 structure EXACTLY): out = max(0, f_c + sum_9 w_o * f_nbr).
//      i-pencil blocks, 128 threads x float4 = full row, NBATCH=4 batches;
//      f rows rotate through 6-wide register windows; zero-register L2
//      prefetch of f row i+2 (R13). Launched with PDL: prologue f loads
//      (independent of g_w) execute concurrently with K1's tail; a single
//      griddepcontrol.wait orders the first weight load after K1.
//      Known-bad (do not retry): shuffles (R5/R8), unroll (R7), bound-5 /
//      staged regs (R10), reg-prefetch (R11), reorder+__ldcs (R12),
//      weight/L1 prefetch & deeper ladders (R14, R16).
// Weight planes: 0:Wc-1 1:Wxp 2:Wxm 3:Wyp 4:Wym 5:Wpp 6:Wpm 7:Wmp 8:Wmm

static constexpr int NXC    = 512;
static constexpr int NYC    = 512;
static constexpr int ICH    = 16;
static constexpr int NBATCH = 4;
static constexpr int TPB    = NYC / 4;      // 128
static constexpr long PLANE = (long)NXC * NYC;

__device__ __nv_bfloat16 g_wh[9 * NXC * NYC];   // 4.7 MB scratch (L2-resident)

// p points at row[j0]; v[m] = p[m-1], halos zero-filled via L/R predicates.
__device__ __forceinline__ void win6_p(const float* __restrict__ p,
                                       bool Lg, bool Rg, float v[6]) {
    const float4 m4 = __ldg(reinterpret_cast<const float4*>(p));
    v[0] = Lg ? __ldg(p - 1) : 0.0f;
    v[1] = m4.x; v[2] = m4.y; v[3] = m4.z; v[4] = m4.w;
    v[5] = Rg ? __ldg(p + 4) : 0.0f;
}

__device__ __forceinline__ void store_w4_bf16(__nv_bfloat16* dst, const float w[4]) {
    __nv_bfloat162 lo = __floats2bfloat162_rn(w[0], w[1]);
    __nv_bfloat162 hi = __floats2bfloat162_rn(w[2], w[3]);
    uint2 st;
    st.x = *reinterpret_cast<const unsigned*>(&lo);
    st.y = *reinterpret_cast<const unsigned*>(&hi);
    *reinterpret_cast<uint2*>(dst) = st;
}

__global__ __launch_bounds__(TPB)
void fp2d_weights_kernel(const float* __restrict__ A,
                         const float* __restrict__ D,
                         const float* __restrict__ dtp) {
    const int tid = threadIdx.x;
    const int j0  = tid * 4;
    const bool L  = (tid > 0);
    const bool R  = (tid < TPB - 1);
    const int i   = blockIdx.x;
    const int grp = blockIdx.y;

    const float dt  = __ldg(dtp);
    const float hdt = 0.5f  * dt;
    const float qdt = 0.25f * dt;

    const float* A0 = A;
    const float* A1 = A + PLANE;
    const float* D0 = D;
    const float* D1 = D + PLANE;
    const float* D2 = D + 2 * PLANE;

    float w0[4], w1[4], w2[4];
    int p0, p1, p2;

    if (grp == 0) {
        // center-row weights: Wc-1 (0), Wyp(3), Wym(4)
        p0 = 0; p1 = 3; p2 = 4;
        const float4 d0 = __ldg(reinterpret_cast<const float4*>(D0 + (long)i * NYC + j0));
        float d1w[6], a1w[6];
        win6_p(D1 + (long)i * NYC + j0, L, R, d1w);
        win6_p(A1 + (long)i * NYC + j0, L, R, a1w);
        const float d0v[4] = {d0.x, d0.y, d0.z, d0.w};
        #pragma unroll
        for (int k = 0; k < 4; ++k) {
            w0[k] = -dt * (d0v[k] + d1w[k + 1]);     // Wc - 1 (small!)
            w1[k] = hdt * (d1w[k + 2] - a1w[k + 2]);
            w2[k] = hdt * (d1w[k]     + a1w[k]);
        }
    } else if (grp == 1) {
        // i+1-row weights: Wxp(1), Wpp(5), Wpm(6)
        p0 = 1; p1 = 5; p2 = 6;
        const int ip = i + 1;
        if (ip < NXC) {
            const float4 a0 = __ldg(reinterpret_cast<const float4*>(A0 + (long)ip * NYC + j0));
            const float4 d0 = __ldg(reinterpret_cast<const float4*>(D0 + (long)ip * NYC + j0));
            const float a0v[4] = {a0.x, a0.y, a0.z, a0.w};
            const float d0v[4] = {d0.x, d0.y, d0.z, d0.w};
            float d2w[6];
            win6_p(D2 + (long)ip * NYC + j0, L, R, d2w);
            #pragma unroll
            for (int k = 0; k < 4; ++k) {
                w0[k] =  hdt * (d0v[k] - a0v[k]);
                w1[k] =  qdt * d2w[k + 2];
                w2[k] = -qdt * d2w[k];
            }
        } else {
            #pragma unroll
            for (int k = 0; k < 4; ++k) { w0[k] = 0.f; w1[k] = 0.f; w2[k] = 0.f; }
        }
    } else {
        // i-1-row weights: Wxm(2), Wmp(7), Wmm(8)
        p0 = 2; p1 = 7; p2 = 8;
        const int im = i - 1;
        if (im >= 0) {
            const float4 a0 = __ldg(reinterpret_cast<const float4*>(A0 + (long)im * NYC + j0));
            const float4 d0 = __ldg(reinterpret_cast<const float4*>(D0 + (long)im * NYC + j0));
            const float a0v[4] = {a0.x, a0.y, a0.z, a0.w};
            const float d0v[4] = {d0.x, d0.y, d0.z, d0.w};
            float d2w[6];
            win6_p(D2 + (long)im * NYC + j0, L, R, d2w);
            #pragma unroll
            for (int k = 0; k < 4; ++k) {
                w0[k] =  hdt * (d0v[k] + a0v[k]);
                w1[k] = -qdt * d2w[k + 2];
                w2[k] =  qdt * d2w[k];
            }
        } else {
            #pragma unroll
            for (int k = 0; k < 4; ++k) { w0[k] = 0.f; w1[k] = 0.f; w2[k] = 0.f; }
        }
    }

    const long off = (long)i * NYC + j0;
    store_w4_bf16(g_wh + p0 * PLANE + off, w0);
    store_w4_bf16(g_wh + p1 * PLANE + off, w1);
    store_w4_bf16(g_wh + p2 * PLANE + off, w2);

    // PDL: allow the step kernel's blocks to launch; its griddepcontrol.wait
    // orders g_wh reads after these stores.
    asm volatile("griddepcontrol.launch_dependents;");
}

__global__ __launch_bounds__(TPB, 4)
void fp2d_step_kernel(const float* __restrict__ f,
                      float* __restrict__ out) {
    const int tid = threadIdx.x;
    const int j0  = tid * 4;
    const bool L  = (tid > 0);
    const bool R  = (tid < TPB - 1);
    const bool pfl = ((tid & 7) == 0);   // one lane per 128B line
    const int i0  = blockIdx.x * ICH;
    const long b0 = (long)blockIdx.y * NBATCH;

    // single base pointers; batch/plane offsets become LDG/STG immediates
    const float* fbase = f   + b0 * PLANE + (long)i0 * NYC + j0;  // row i0
    float*       obase = out + b0 * PLANE + (long)i0 * NYC + j0;
    const __nv_bfloat16* wbase = g_wh + (long)i0 * NYC + j0;

    // f windows: [m] = f[row][j0+m-1], rotated along i
    float fm[NBATCH][6], fc[NBATCH][6], fp[NBATCH][6];

    // ---------------- prologue: f rows i0-1 and i0 (independent of g_wh,
    // runs concurrently with the weights kernel's tail under PDL) ----------
    if (i0 > 0) {
        #pragma unroll
        for (int b = 0; b < NBATCH; ++b)
            win6_p(fbase + b * PLANE - NYC, L, R, fm[b]);
    } else {
        #pragma unroll
        for (int b = 0; b < NBATCH; ++b)
            #pragma unroll
            for (int m = 0; m < 6; ++m) fm[b][m] = 0.0f;
    }
    #pragma unroll
    for (int b = 0; b < NBATCH; ++b)
        win6_p(fbase + b * PLANE, L, R, fc[b]);

    // PDL: order all g_wh reads after the weights kernel's stores.
    asm volatile("griddepcontrol.wait;");

    // ---------------- main i-march ----------------
    for (int it = 0; it < ICH; ++it) {
        const bool up_ok = (i0 + it + 1) < NXC;

        // 1) load f row i+1 (the only DRAM-new data this iteration)
        if (up_ok) {
            #pragma unroll
            for (int b = 0; b < NBATCH; ++b)
                win6_p(fbase + b * PLANE + NYC, L, R, fp[b]);
        } else {
            #pragma unroll
            for (int b = 0; b < NBATCH; ++b)
                #pragma unroll
                for (int m = 0; m < 6; ++m) fp[b][m] = 0.0f;
        }

        // 1b) zero-register L2 prefetch of f row i+2 (R13, proven)
        if (pfl && ((i0 + it + 2) < NXC)) {
            #pragma unroll
            for (int b = 0; b < NBATCH; ++b) {
                const float* pp = fbase + b * PLANE + 2 * NYC;
                asm volatile("prefetch.global.L2 [%0];" :: "l"(pp));
            }
        }

        // 2) load the 9 bf16 weight vectors for row i (L2-hot, 8B each)
        uint2 wr[9];
        #pragma unroll
        for (int p = 0; p < 9; ++p)
            wr[p] = __ldg(reinterpret_cast<const uint2*>(wbase + p * PLANE));
        float wf[9][4];
        #pragma unroll
        for (int p = 0; p < 9; ++p) {
            const __nv_bfloat162 lo = *reinterpret_cast<const __nv_bfloat162*>(&wr[p].x);
            const __nv_bfloat162 hi = *reinterpret_cast<const __nv_bfloat162*>(&wr[p].y);
            const float2 flo = __bfloat1622float2(lo);
            const float2 fhi = __bfloat1622float2(hi);
            wf[p][0] = flo.x; wf[p][1] = flo.y;
            wf[p][2] = fhi.x; wf[p][3] = fhi.y;
        }

        // 3) compute + streaming-store outputs for row i
        //    v = f_c + (Wc-1)*f_c + axis/diag terms   (Wc split for bf16)
        #pragma unroll
        for (int b = 0; b < NBATCH; ++b) {
            float rv[4];
            #pragma unroll
            for (int k = 0; k < 4; ++k) {
                float v = fc[b][k + 1];
                v += wf[0][k] * fc[b][k + 1];
                v += wf[1][k] * fp[b][k + 1];
                v += wf[2][k] * fm[b][k + 1];
                v += wf[3][k] * fc[b][k + 2];
                v += wf[4][k] * fc[b][k];
                v += wf[5][k] * fp[b][k + 2];
                v += wf[6][k] * fp[b][k];
                v += wf[7][k] * fm[b][k + 2];
                v += wf[8][k] * fm[b][k];
                rv[k] = fmaxf(v, 0.0f);
            }
            float4 res;
            res.x = rv[0]; res.y = rv[1]; res.z = rv[2]; res.w = rv[3];
            __stcs(reinterpret_cast<float4*>(obase + b * PLANE), res);
        }

        // 4) rotate f windows (fp -> fc -> fm), advance bases
        #pragma unroll
        for (int b = 0; b < NBATCH; ++b)
            #pragma unroll
            for (int m = 0; m < 6; ++m) {
                fm[b][m] = fc[b][m];
                fc[b][m] = fp[b][m];
            }
        fbase += NYC;
        obase += NYC;
        wbase += NYC;
    }
}

extern "C" void kernel_launch(void* const* d_in, const int* in_sizes, int n_in,
                              void* d_out, int out_size) {
    const float* f  = (const float*)d_in[0];
    const float* A  = (const float*)d_in[1];
    const float* D  = (const float*)d_in[2];
    const float* dt = (const float*)d_in[3];
    float* out = (float*)d_out;

    const int plane = NXC * NYC;
    const int B = in_sizes[0] / plane;   // 128

    dim3 wgrid(NXC, 3);
    fp2d_weights_kernel<<<wgrid, TPB>>>(A, D, dt);

    // step kernel with Programmatic Dependent Launch: its blocks may launch
    // while the weights kernel drains; griddepcontrol.wait provides ordering.
    dim3 grid(NXC / ICH, B / NBATCH);    // (32, 32)
    cudaLaunchConfig_t cfg = {};
    cfg.gridDim  = grid;
    cfg.blockDim = dim3(TPB, 1, 1);
    cudaLaunchAttribute attrs[1];
    attrs[0].id = cudaLaunchAttributeProgrammaticStreamSerialization;
    attrs[0].val.programmaticStreamSerializationAllowed = 1;
    cfg.attrs = attrs;
    cfg.numAttrs = 1;
    cudaLaunchKernelEx(&cfg, fp2d_step_kernel, f, out);
}